// round 14
// baseline (speedup 1.0000x reference)
#include <cuda_runtime.h>
#include <cuda_bf16.h>
#include <stdint.h>
#include <math.h>

#define Bn 128
#define Tn 512
#define Dn 256
#define Hn 512
#define G4 2048

__device__ float g_zx[(size_t)Tn * Bn * G4];
__device__ __align__(16) __nv_bfloat16 g_WhT1[(size_t)G4 * Hn];  // [n][k] hi split
__device__ __align__(16) __nv_bfloat16 g_WhT2[(size_t)G4 * Hn];  // [n][k] lo split
__device__ __align__(16) __nv_bfloat16 g_h1[2][Bn * Hn];
__device__ __align__(16) __nv_bfloat16 g_h2[2][Bn * Hn];
__device__ float g_c[Bn * Hn];

__device__ __forceinline__ uint32_t smem_u32(const void* p) {
    uint32_t a;
    asm("{ .reg .u64 t; cvta.to.shared.u64 t, %1; cvt.u32.u64 %0, t; }" : "=r"(a) : "l"(p));
    return a;
}

#define CP_ASYNC16(dst, src) \
    asm volatile("cp.async.cg.shared.global [%0], [%1], 16;" :: "r"(dst), "l"(src) : "memory")
#define CP_COMMIT() asm volatile("cp.async.commit_group;" ::: "memory")
#define CP_WAIT0()  asm volatile("cp.async.wait_group 0;" ::: "memory")
#define CP_WAIT1()  asm volatile("cp.async.wait_group 1;" ::: "memory")

__device__ __forceinline__ void ldsm_x4(uint32_t* r, uint32_t addr) {
    asm volatile("ldmatrix.sync.aligned.m8n8.x4.shared.b16 {%0,%1,%2,%3}, [%4];"
                 : "=r"(r[0]), "=r"(r[1]), "=r"(r[2]), "=r"(r[3]) : "r"(addr));
}

__device__ __forceinline__ void mma_bf16(float* c, const uint32_t* a, const uint32_t* b) {
    asm volatile(
        "mma.sync.aligned.m16n8k16.row.col.f32.bf16.bf16.f32 "
        "{%0,%1,%2,%3}, {%4,%5,%6,%7}, {%8,%9}, {%0,%1,%2,%3};"
        : "+f"(c[0]), "+f"(c[1]), "+f"(c[2]), "+f"(c[3])
        : "r"(a[0]), "r"(a[1]), "r"(a[2]), "r"(a[3]), "r"(b[0]), "r"(b[1]));
}

// ---------------------------------------------------------------------------
// prep: split & transpose Wh -> WhT1/WhT2 ([n][k] bf16)
// ---------------------------------------------------------------------------
__global__ void prep_split_kernel(const float* __restrict__ Wh) {
    int idx = blockIdx.x * 512 + threadIdx.x;
    int n = idx >> 9;
    int k = idx & 511;
    float w = Wh[(size_t)k * G4 + n];
    __nv_bfloat16 w1 = __float2bfloat16(w);
    g_WhT1[(size_t)n * Hn + k] = w1;
    g_WhT2[(size_t)n * Hn + k] = __float2bfloat16(w - __bfloat162float(w1));
}

__global__ void init_state_kernel() {
    int i = blockIdx.x * blockDim.x + threadIdx.x;
    if (i < Bn * Hn) {
        g_h1[0][i] = __float2bfloat16(0.0f);
        g_h2[0][i] = __float2bfloat16(0.0f);
        g_c[i] = 0.0f;
    }
}

// ---------------------------------------------------------------------------
// zx = x @ Wx + b  (fp32 SIMT, 128x64 tiles, 8x4 micro-tile)
// ---------------------------------------------------------------------------
__global__ __launch_bounds__(256) void zx_kernel(
    const float* __restrict__ x, const float* __restrict__ Wx,
    const float* __restrict__ bias)
{
    __shared__ __align__(16) float As[16][132];
    __shared__ __align__(16) float Bs[16][64];
    int tid = threadIdx.x;
    int tx = tid & 15, ty = tid >> 4;
    int mbase = blockIdx.y * 128, nbase = blockIdx.x * 64;
    float acc[8][4] = {};

    for (int kb = 0; kb < Dn; kb += 16) {
        int ka = tid & 15, ma0 = tid >> 4;
        #pragma unroll
        for (int p = 0; p < 8; p++)
            As[ka][ma0 + p * 16] = x[(size_t)(mbase + ma0 + p * 16) * Dn + kb + ka];
        int kk0 = tid >> 6, c = tid & 63;
        #pragma unroll
        for (int p = 0; p < 4; p++)
            Bs[kk0 + p * 4][c] = Wx[(size_t)(kb + kk0 + p * 4) * G4 + nbase + c];
        __syncthreads();
        #pragma unroll
        for (int kk = 0; kk < 16; kk++) {
            float4 b4 = *reinterpret_cast<const float4*>(&Bs[kk][tx * 4]);
            float4 a0 = *reinterpret_cast<const float4*>(&As[kk][ty * 8]);
            float4 a1 = *reinterpret_cast<const float4*>(&As[kk][ty * 8 + 4]);
            float av[8] = {a0.x,a0.y,a0.z,a0.w,a1.x,a1.y,a1.z,a1.w};
            float bv[4] = {b4.x,b4.y,b4.z,b4.w};
            #pragma unroll
            for (int v = 0; v < 8; v++)
                #pragma unroll
                for (int u = 0; u < 4; u++)
                    acc[v][u] += av[v] * bv[u];
        }
        __syncthreads();
    }
    float bb[4];
    #pragma unroll
    for (int u = 0; u < 4; u++) bb[u] = bias[nbase + tx * 4 + u];
    #pragma unroll
    for (int v = 0; v < 8; v++) {
        int m = mbase + ty * 8 + v;    // m = b*T + t
        int b = m >> 9, t = m & 511;
        float4 o = {acc[v][0]+bb[0], acc[v][1]+bb[1], acc[v][2]+bb[2], acc[v][3]+bb[3]};
        *reinterpret_cast<float4*>(&g_zx[((size_t)t * Bn + b) * G4 + nbase + tx * 4]) = o;
    }
}

// ---------------------------------------------------------------------------
// LSTM step via mma.sync bf16 (2-way split, 3 products, fp32 accum).
// Grid (64 j-blocks x 2 m-halves) = 128 CTAs x 256 thr.
// CTA: C tile 64(m) x 32(n: 4 gates x 8 j), K=512 in 8 cp.async chunks.
// ---------------------------------------------------------------------------
// smem layout (bytes), rows padded to 144B (72 bf16) for conflict-free ldmatrix
#define AS_OFF 0        // [buf][split][64 rows][144B]  2*2*9216 = 36864
#define BS_OFF 36864    // [buf][split][32 rows][144B]  2*2*4608 = 18432
#define ZS_OFF 55296    // [64][33] fp32 = 8448
#define SMEM_STEP (55296 + 8448)

__device__ __forceinline__ void stage_chunk(
    uint32_t sb, int buf, int kbase, int m0, int j0,
    const __nv_bfloat16* __restrict__ h1,
    const __nv_bfloat16* __restrict__ h2, int tid)
{
    // A: 2 splits x 64 rows x 8 granules = 1024
    #pragma unroll
    for (int i = 0; i < 4; i++) {
        int l = tid + i * 256;
        int s = l >> 9, w = l & 511;
        int row = w >> 3, q = w & 7;
        const __nv_bfloat16* src = (s ? h2 : h1) + (m0 + row) * Hn + kbase + q * 8;
        uint32_t dst = sb + AS_OFF + buf * 18432 + s * 9216 + row * 144 + q * 16;
        CP_ASYNC16(dst, src);
    }
    // B: 2 splits x 32 rows x 8 granules = 512
    #pragma unroll
    for (int i = 0; i < 2; i++) {
        int l = tid + i * 256;
        int s = l >> 8, w = l & 255;
        int row = w >> 3, q = w & 7;           // row = gate*8 + jj
        int grow = ((row >> 3) << 9) + j0 + (row & 7);
        const __nv_bfloat16* src = (s ? g_WhT2 : g_WhT1) + (size_t)grow * Hn + kbase + q * 8;
        uint32_t dst = sb + BS_OFF + buf * 9216 + s * 4608 + row * 144 + q * 16;
        CP_ASYNC16(dst, src);
    }
}

__global__ __launch_bounds__(256, 1) void step_kernel(float* __restrict__ out, int t) {
    extern __shared__ char smem_raw[];
    uint32_t sb = smem_u32(smem_raw);
    float* zs = reinterpret_cast<float*>(smem_raw + ZS_OFF);

    int tid = threadIdx.x;
    int wid = tid >> 5, lane = tid & 31;
    int j0 = blockIdx.x * 8;
    int m0 = blockIdx.y * 64;

    const __nv_bfloat16* h1 = g_h1[t & 1];
    const __nv_bfloat16* h2 = g_h2[t & 1];
    __nv_bfloat16* h1n = g_h1[(t + 1) & 1];
    __nv_bfloat16* h2n = g_h2[(t + 1) & 1];

    int mw = (wid & 3) * 16;        // warp m-subtile
    int nw = (wid >> 2) * 16;       // warp n-subtile (2 mma n-tiles)

    // ldmatrix lane addresses (byte offsets within a [rows][144B] tile)
    uint32_t a_lane = (mw + (lane & 15)) * 144 + (lane >> 4) * 16;
    uint32_t b_lane = (nw + (lane & 7) + ((lane >> 4) << 3)) * 144 + (((lane >> 3) & 1) << 4);

    float c0[4] = {}, c1[4] = {};   // two 16x8 accum tiles

    stage_chunk(sb, 0, 0, m0, j0, h1, h2, tid);
    CP_COMMIT();

    #pragma unroll 1
    for (int ch = 0; ch < 8; ch++) {
        if (ch + 1 < 8) {
            stage_chunk(sb, (ch + 1) & 1, (ch + 1) * 64, m0, j0, h1, h2, tid);
            CP_COMMIT();
            CP_WAIT1();
        } else {
            CP_WAIT0();
        }
        __syncthreads();

        uint32_t abase = sb + AS_OFF + (ch & 1) * 18432 + a_lane;
        uint32_t bbase = sb + BS_OFF + (ch & 1) * 9216 + b_lane;
        #pragma unroll
        for (int k0 = 0; k0 < 4; k0++) {
            uint32_t kb = k0 * 32;
            uint32_t a1[4], a2[4], b1[4], b2[4];
            ldsm_x4(a1, abase + kb);
            ldsm_x4(a2, abase + 9216 + kb);
            ldsm_x4(b1, bbase + kb);
            ldsm_x4(b2, bbase + 4608 + kb);
            mma_bf16(c0, a1, b1);     mma_bf16(c1, a1, b1 + 2);
            mma_bf16(c0, a1, b2);     mma_bf16(c1, a1, b2 + 2);
            mma_bf16(c0, a2, b1);     mma_bf16(c1, a2, b1 + 2);
        }
        __syncthreads();
    }

    // write C fragments to zs[64][33]
    {
        int row = mw + (lane >> 2);
        int col = nw + (lane & 3) * 2;
        zs[row * 33 + col]           = c0[0];
        zs[row * 33 + col + 1]       = c0[1];
        zs[(row + 8) * 33 + col]     = c0[2];
        zs[(row + 8) * 33 + col + 1] = c0[3];
        zs[row * 33 + col + 8]           = c1[0];
        zs[row * 33 + col + 9]           = c1[1];
        zs[(row + 8) * 33 + col + 8]     = c1[2];
        zs[(row + 8) * 33 + col + 9]     = c1[3];
    }
    __syncthreads();

    // fused gate epilogue: 2 (m,j) pairs per thread
    int jj = tid & 7;
    int j = j0 + jj;
    #pragma unroll
    for (int r = 0; r < 2; r++) {
        int mloc = (tid >> 3) + r * 32;
        int m = m0 + mloc;
        const float* zxr = &g_zx[((size_t)t * Bn + m) * G4];

        float vi = zs[mloc * 33 + 0 * 8 + jj] + zxr[0 * Hn + j];
        float vf = zs[mloc * 33 + 1 * 8 + jj] + zxr[1 * Hn + j];
        float vg = zs[mloc * 33 + 2 * 8 + jj] + zxr[2 * Hn + j];
        float vo = zs[mloc * 33 + 3 * 8 + jj] + zxr[3 * Hn + j];

        float ig = 1.0f / (1.0f + __expf(-vi));
        float fg = 1.0f / (1.0f + __expf(-vf));
        float gg = tanhf(vg);
        float og = 1.0f / (1.0f + __expf(-vo));

        int sidx = m * Hn + j;
        float cnew = fg * g_c[sidx] + ig * gg;
        float hnew = og * tanhf(cnew);
        g_c[sidx] = cnew;

        __nv_bfloat16 hv1 = __float2bfloat16(hnew);
        h1n[sidx] = hv1;
        h2n[sidx] = __float2bfloat16(hnew - __bfloat162float(hv1));

        out[((size_t)m * Tn + t) * Hn + j] = hnew;
        if (t == Tn - 1) {
            size_t tail = (size_t)Bn * Tn * Hn;
            out[tail + (size_t)m * Hn + j] = hnew;
            out[tail + (size_t)Bn * Hn + (size_t)m * Hn + j] = cnew;
        }
    }
}

// ---------------------------------------------------------------------------
extern "C" void kernel_launch(void* const* d_in, const int* in_sizes, int n_in,
                              void* d_out, int out_size) {
    const float* x  = (const float*)d_in[0];
    const float* Wx = (const float*)d_in[1];
    const float* Wh = (const float*)d_in[2];
    const float* b  = (const float*)d_in[3];
    float* out = (float*)d_out;

    cudaFuncSetAttribute(step_kernel, cudaFuncAttributeMaxDynamicSharedMemorySize, SMEM_STEP);

    init_state_kernel<<<(Bn * Hn + 255) / 256, 256>>>();
    prep_split_kernel<<<(G4 * Hn) / 512, 512>>>(Wh);

    dim3 zgrid(G4 / 64, (Bn * Tn) / 128);
    zx_kernel<<<zgrid, 256>>>(x, Wx, b);

    dim3 sgrid(64, 2);
    for (int t = 0; t < Tn; t++) {
        step_kernel<<<sgrid, 256, SMEM_STEP>>>(out, t);
    }
}

// round 15
// speedup vs baseline: 1.0326x; 1.0326x over previous
#include <cuda_runtime.h>
#include <cuda_bf16.h>
#include <stdint.h>
#include <math.h>

#define Bn 128
#define Tn 512
#define Dn 256
#define Hn 512
#define G4 2048

__device__ float g_zx[(size_t)Tn * Bn * G4];
__device__ __align__(16) __nv_bfloat16 g_WhT1[(size_t)G4 * Hn];  // [n][k] hi split
__device__ __align__(16) __nv_bfloat16 g_WhT2[(size_t)G4 * Hn];  // [n][k] lo split
__device__ __align__(16) __nv_bfloat16 g_h1[2][Bn * Hn];
__device__ __align__(16) __nv_bfloat16 g_h2[2][Bn * Hn];
__device__ float g_c[Bn * Hn];

__device__ __forceinline__ uint32_t smem_u32(const void* p) {
    uint32_t a;
    asm("{ .reg .u64 t; cvta.to.shared.u64 t, %1; cvt.u32.u64 %0, t; }" : "=r"(a) : "l"(p));
    return a;
}

#define CP_ASYNC16(dst, src) \
    asm volatile("cp.async.cg.shared.global [%0], [%1], 16;" :: "r"(dst), "l"(src) : "memory")
#define CP_COMMIT() asm volatile("cp.async.commit_group;" ::: "memory")
#define CP_WAIT0()  asm volatile("cp.async.wait_group 0;" ::: "memory")
#define CP_WAIT1()  asm volatile("cp.async.wait_group 1;" ::: "memory")

__device__ __forceinline__ void ldsm_x4(uint32_t* r, uint32_t addr) {
    asm volatile("ldmatrix.sync.aligned.m8n8.x4.shared.b16 {%0,%1,%2,%3}, [%4];"
                 : "=r"(r[0]), "=r"(r[1]), "=r"(r[2]), "=r"(r[3]) : "r"(addr));
}

__device__ __forceinline__ void mma_bf16(float* c, const uint32_t* a, const uint32_t* b) {
    asm volatile(
        "mma.sync.aligned.m16n8k16.row.col.f32.bf16.bf16.f32 "
        "{%0,%1,%2,%3}, {%4,%5,%6,%7}, {%8,%9}, {%0,%1,%2,%3};"
        : "+f"(c[0]), "+f"(c[1]), "+f"(c[2]), "+f"(c[3])
        : "r"(a[0]), "r"(a[1]), "r"(a[2]), "r"(a[3]), "r"(b[0]), "r"(b[1]));
}

// ---------------------------------------------------------------------------
// prep: split & transpose Wh -> WhT1/WhT2 ([n][k] bf16)
// ---------------------------------------------------------------------------
__global__ void prep_split_kernel(const float* __restrict__ Wh) {
    int idx = blockIdx.x * 512 + threadIdx.x;
    int n = idx >> 9;
    int k = idx & 511;
    float w = Wh[(size_t)k * G4 + n];
    __nv_bfloat16 w1 = __float2bfloat16(w);
    g_WhT1[(size_t)n * Hn + k] = w1;
    g_WhT2[(size_t)n * Hn + k] = __float2bfloat16(w - __bfloat162float(w1));
}

__global__ void init_state_kernel() {
    int i = blockIdx.x * blockDim.x + threadIdx.x;
    if (i < Bn * Hn) {
        g_h1[0][i] = __float2bfloat16(0.0f);
        g_h2[0][i] = __float2bfloat16(0.0f);
        g_c[i] = 0.0f;
    }
}

// ---------------------------------------------------------------------------
// zx = x @ Wx + b  (fp32 SIMT, 128x64 tiles, 8x4 micro-tile)
// ---------------------------------------------------------------------------
__global__ __launch_bounds__(256) void zx_kernel(
    const float* __restrict__ x, const float* __restrict__ Wx,
    const float* __restrict__ bias)
{
    __shared__ __align__(16) float As[16][132];
    __shared__ __align__(16) float Bs[16][64];
    int tid = threadIdx.x;
    int tx = tid & 15, ty = tid >> 4;
    int mbase = blockIdx.y * 128, nbase = blockIdx.x * 64;
    float acc[8][4] = {};

    for (int kb = 0; kb < Dn; kb += 16) {
        int ka = tid & 15, ma0 = tid >> 4;
        #pragma unroll
        for (int p = 0; p < 8; p++)
            As[ka][ma0 + p * 16] = x[(size_t)(mbase + ma0 + p * 16) * Dn + kb + ka];
        int kk0 = tid >> 6, c = tid & 63;
        #pragma unroll
        for (int p = 0; p < 4; p++)
            Bs[kk0 + p * 4][c] = Wx[(size_t)(kb + kk0 + p * 4) * G4 + nbase + c];
        __syncthreads();
        #pragma unroll
        for (int kk = 0; kk < 16; kk++) {
            float4 b4 = *reinterpret_cast<const float4*>(&Bs[kk][tx * 4]);
            float4 a0 = *reinterpret_cast<const float4*>(&As[kk][ty * 8]);
            float4 a1 = *reinterpret_cast<const float4*>(&As[kk][ty * 8 + 4]);
            float av[8] = {a0.x,a0.y,a0.z,a0.w,a1.x,a1.y,a1.z,a1.w};
            float bv[4] = {b4.x,b4.y,b4.z,b4.w};
            #pragma unroll
            for (int v = 0; v < 8; v++)
                #pragma unroll
                for (int u = 0; u < 4; u++)
                    acc[v][u] += av[v] * bv[u];
        }
        __syncthreads();
    }
    float bb[4];
    #pragma unroll
    for (int u = 0; u < 4; u++) bb[u] = bias[nbase + tx * 4 + u];
    #pragma unroll
    for (int v = 0; v < 8; v++) {
        int m = mbase + ty * 8 + v;    // m = b*T + t
        int b = m >> 9, t = m & 511;
        float4 o = {acc[v][0]+bb[0], acc[v][1]+bb[1], acc[v][2]+bb[2], acc[v][3]+bb[3]};
        *reinterpret_cast<float4*>(&g_zx[((size_t)t * Bn + b) * G4 + nbase + tx * 4]) = o;
    }
}

// ---------------------------------------------------------------------------
// LSTM step via mma.sync bf16 (2-way split, 3 products, fp32 accum).
// Grid (64 j-blocks x 2 m-halves) = 128 CTAs x 256 thr.
// CTA: C tile 64(m) x 32(n: 4 gates x 8 j), K=512 in 8 cp.async chunks.
// ---------------------------------------------------------------------------
// smem layout (bytes), rows padded to 144B (72 bf16) for conflict-free ldmatrix
#define AS_OFF 0        // [buf][split][64 rows][144B]  2*2*9216 = 36864
#define BS_OFF 36864    // [buf][split][32 rows][144B]  2*2*4608 = 18432
#define ZS_OFF 55296    // [64][33] fp32 = 8448
#define SMEM_STEP (55296 + 8448)

__device__ __forceinline__ void stage_chunk(
    uint32_t sb, int buf, int kbase, int m0, int j0,
    const __nv_bfloat16* __restrict__ h1,
    const __nv_bfloat16* __restrict__ h2, int tid)
{
    // A: 2 splits x 64 rows x 8 granules = 1024
    #pragma unroll
    for (int i = 0; i < 4; i++) {
        int l = tid + i * 256;
        int s = l >> 9, w = l & 511;
        int row = w >> 3, q = w & 7;
        const __nv_bfloat16* src = (s ? h2 : h1) + (m0 + row) * Hn + kbase + q * 8;
        uint32_t dst = sb + AS_OFF + buf * 18432 + s * 9216 + row * 144 + q * 16;
        CP_ASYNC16(dst, src);
    }
    // B: 2 splits x 32 rows x 8 granules = 512
    #pragma unroll
    for (int i = 0; i < 2; i++) {
        int l = tid + i * 256;
        int s = l >> 8, w = l & 255;
        int row = w >> 3, q = w & 7;           // row = gate*8 + jj
        int grow = ((row >> 3) << 9) + j0 + (row & 7);
        const __nv_bfloat16* src = (s ? g_WhT2 : g_WhT1) + (size_t)grow * Hn + kbase + q * 8;
        uint32_t dst = sb + BS_OFF + buf * 9216 + s * 4608 + row * 144 + q * 16;
        CP_ASYNC16(dst, src);
    }
}

__global__ __launch_bounds__(256, 1) void step_kernel(float* __restrict__ out, int t) {
    extern __shared__ char smem_raw[];
    uint32_t sb = smem_u32(smem_raw);
    float* zs = reinterpret_cast<float*>(smem_raw + ZS_OFF);

    int tid = threadIdx.x;
    int wid = tid >> 5, lane = tid & 31;
    int j0 = blockIdx.x * 8;
    int m0 = blockIdx.y * 64;

    const __nv_bfloat16* h1 = g_h1[t & 1];
    const __nv_bfloat16* h2 = g_h2[t & 1];
    __nv_bfloat16* h1n = g_h1[(t + 1) & 1];
    __nv_bfloat16* h2n = g_h2[(t + 1) & 1];

    int mw = (wid & 3) * 16;        // warp m-subtile
    int nw = (wid >> 2) * 16;       // warp n-subtile (2 mma n-tiles)

    // ldmatrix lane addresses (byte offsets within a [rows][144B] tile)
    uint32_t a_lane = (mw + (lane & 15)) * 144 + (lane >> 4) * 16;
    uint32_t b_lane = (nw + (lane & 7) + ((lane >> 4) << 3)) * 144 + (((lane >> 3) & 1) << 4);

    float c0[4] = {}, c1[4] = {};   // two 16x8 accum tiles

    stage_chunk(sb, 0, 0, m0, j0, h1, h2, tid);
    CP_COMMIT();

    #pragma unroll 1
    for (int ch = 0; ch < 8; ch++) {
        if (ch + 1 < 8) {
            stage_chunk(sb, (ch + 1) & 1, (ch + 1) * 64, m0, j0, h1, h2, tid);
            CP_COMMIT();
            CP_WAIT1();
        } else {
            CP_WAIT0();
        }
        __syncthreads();

        uint32_t abase = sb + AS_OFF + (ch & 1) * 18432 + a_lane;
        uint32_t bbase = sb + BS_OFF + (ch & 1) * 9216 + b_lane;
        #pragma unroll
        for (int k0 = 0; k0 < 4; k0++) {
            uint32_t kb = k0 * 32;
            uint32_t a1[4], a2[4], b1[4], b2[4];
            ldsm_x4(a1, abase + kb);
            ldsm_x4(a2, abase + 9216 + kb);
            ldsm_x4(b1, bbase + kb);
            ldsm_x4(b2, bbase + 4608 + kb);
            mma_bf16(c0, a1, b1);     mma_bf16(c1, a1, b1 + 2);
            mma_bf16(c0, a1, b2);     mma_bf16(c1, a1, b2 + 2);
            mma_bf16(c0, a2, b1);     mma_bf16(c1, a2, b1 + 2);
        }
        __syncthreads();
    }

    // write C fragments to zs[64][33]
    {
        int row = mw + (lane >> 2);
        int col = nw + (lane & 3) * 2;
        zs[row * 33 + col]           = c0[0];
        zs[row * 33 + col + 1]       = c0[1];
        zs[(row + 8) * 33 + col]     = c0[2];
        zs[(row + 8) * 33 + col + 1] = c0[3];
        zs[row * 33 + col + 8]           = c1[0];
        zs[row * 33 + col + 9]           = c1[1];
        zs[(row + 8) * 33 + col + 8]     = c1[2];
        zs[(row + 8) * 33 + col + 9]     = c1[3];
    }
    __syncthreads();

    // fused gate epilogue: 2 (m,j) pairs per thread
    int jj = tid & 7;
    int j = j0 + jj;
    #pragma unroll
    for (int r = 0; r < 2; r++) {
        int mloc = (tid >> 3) + r * 32;
        int m = m0 + mloc;
        const float* zxr = &g_zx[((size_t)t * Bn + m) * G4];

        float vi = zs[mloc * 33 + 0 * 8 + jj] + zxr[0 * Hn + j];
        float vf = zs[mloc * 33 + 1 * 8 + jj] + zxr[1 * Hn + j];
        float vg = zs[mloc * 33 + 2 * 8 + jj] + zxr[2 * Hn + j];
        float vo = zs[mloc * 33 + 3 * 8 + jj] + zxr[3 * Hn + j];

        float ig = 1.0f / (1.0f + __expf(-vi));
        float fg = 1.0f / (1.0f + __expf(-vf));
        float gg = tanhf(vg);
        float og = 1.0f / (1.0f + __expf(-vo));

        int sidx = m * Hn + j;
        float cnew = fg * g_c[sidx] + ig * gg;
        float hnew = og * tanhf(cnew);
        g_c[sidx] = cnew;

        __nv_bfloat16 hv1 = __float2bfloat16(hnew);
        h1n[sidx] = hv1;
        h2n[sidx] = __float2bfloat16(hnew - __bfloat162float(hv1));

        out[((size_t)m * Tn + t) * Hn + j] = hnew;
        if (t == Tn - 1) {
            size_t tail = (size_t)Bn * Tn * Hn;
            out[tail + (size_t)m * Hn + j] = hnew;
            out[tail + (size_t)Bn * Hn + (size_t)m * Hn + j] = cnew;
        }
    }
}

// ---------------------------------------------------------------------------
extern "C" void kernel_launch(void* const* d_in, const int* in_sizes, int n_in,
                              void* d_out, int out_size) {
    const float* x  = (const float*)d_in[0];
    const float* Wx = (const float*)d_in[1];
    const float* Wh = (const float*)d_in[2];
    const float* b  = (const float*)d_in[3];
    float* out = (float*)d_out;

    cudaFuncSetAttribute(step_kernel, cudaFuncAttributeMaxDynamicSharedMemorySize, SMEM_STEP);

    init_state_kernel<<<(Bn * Hn + 255) / 256, 256>>>();
    prep_split_kernel<<<(G4 * Hn) / 512, 512>>>(Wh);

    dim3 zgrid(G4 / 64, (Bn * Tn) / 128);
    zx_kernel<<<zgrid, 256>>>(x, Wx, b);

    dim3 sgrid(64, 2);
    for (int t = 0; t < Tn; t++) {
        step_kernel<<<sgrid, 256, SMEM_STEP>>>(out, t);
    }
}